// round 1
// baseline (speedup 1.0000x reference)
#include <cuda_runtime.h>

// StructuredPruningIF: integrate-and-fire over T=4 timesteps.
// x: [T*B, C, H, W] fp32, T=4 -> per-element recurrence:
//   mem = 0.5*thre; for t: mem += x[t]; spike = (mem >= thre)?thre:0; mem -= spike
// out[t] = spike, laid out with the same T-major stride as x.
//
// Pure streaming: 256MB in + 256MB out. One thread handles one float4 lane
// across all 4 timesteps; the 4 timestep loads are independent (MLP=4).

#define T_STEPS 4

__global__ __launch_bounds__(256) void if_kernel(
    const float4* __restrict__ x,
    const float* __restrict__ thresh,
    float4* __restrict__ out,
    int n4,          // spatial float4 count per timestep
    int stride4)     // float4 stride between timesteps (== n4)
{
    int i = blockIdx.x * blockDim.x + threadIdx.x;
    if (i >= n4) return;

    const float thre = __ldg(thresh);

    // Load all 4 timesteps up front (independent -> overlapped HBM latency)
    float4 xt0 = x[0 * (long)stride4 + i];
    float4 xt1 = x[1 * (long)stride4 + i];
    float4 xt2 = x[2 * (long)stride4 + i];
    float4 xt3 = x[3 * (long)stride4 + i];

    float4 mem = make_float4(0.5f * thre, 0.5f * thre, 0.5f * thre, 0.5f * thre);

    float4 xts[T_STEPS] = {xt0, xt1, xt2, xt3};

#pragma unroll
    for (int t = 0; t < T_STEPS; t++) {
        float4 xt = xts[t];
        float4 spike;

        mem.x += xt.x;
        spike.x = (mem.x >= thre) ? thre : 0.0f;
        mem.x -= spike.x;

        mem.y += xt.y;
        spike.y = (mem.y >= thre) ? thre : 0.0f;
        mem.y -= spike.y;

        mem.z += xt.z;
        spike.z = (mem.z >= thre) ? thre : 0.0f;
        mem.z -= spike.z;

        mem.w += xt.w;
        spike.w = (mem.w >= thre) ? thre : 0.0f;
        mem.w -= spike.w;

        out[t * (long)stride4 + i] = spike;
    }
}

extern "C" void kernel_launch(void* const* d_in, const int* in_sizes, int n_in,
                              void* d_out, int out_size) {
    const float* x      = (const float*)d_in[0];   // [512,128,32,32]
    const float* thresh = (const float*)d_in[1];   // [1]
    float* out          = (float*)d_out;

    int total = in_sizes[0];            // 67,108,864
    int per_t = total / T_STEPS;        // 16,777,216
    int n4 = per_t / 4;                 // 4,194,304 float4 lanes

    int threads = 256;
    int blocks = (n4 + threads - 1) / threads;
    if_kernel<<<blocks, threads>>>((const float4*)x, thresh, (float4*)out,
                                   n4, n4);
}